// round 7
// baseline (speedup 1.0000x reference)
#include <cuda_runtime.h>

typedef unsigned long long ull;

#define B_TOT 512
#define T_LEN 1000
#define IN_D  26
#define H1_D  64
#define H2_D  32
#define F1_D  16
#define OUT_D 10

#define S_PER 4                  // samples per block
#define NBLK  (B_TOT / S_PER)    // 128 blocks -> one wave
#define NTHR  576                // 18 warps: 12x L1 (3 k-splits), 6x L2 (3 k-splits)
#define CHUNK 16

// ---- f32x2 packed helpers ----
__device__ __forceinline__ ull pk2(float lo, float hi) {
    ull r; asm("mov.b64 %0, {%1, %2};" : "=l"(r) : "f"(lo), "f"(hi)); return r;
}
__device__ __forceinline__ float2 unpk(ull v) {
    float2 r; asm("mov.b64 {%0, %1}, %2;" : "=f"(r.x), "=f"(r.y) : "l"(v)); return r;
}
__device__ __forceinline__ ull fma2(ull a, ull b, ull c) {
    ull d; asm("fma.rn.f32x2 %0, %1, %2, %3;" : "=l"(d) : "l"(a), "l"(b), "l"(c)); return d;
}

__device__ __forceinline__ float sigm(float xv) {
    float e = __expf(-xv);
    return __fdividef(1.0f, 1.0f + e);
}
__device__ __forceinline__ float tanh_(float xv) {
    float a = fabsf(xv);
    float e = __expf(2.0f * a);
    float r = 1.0f - __fdividef(2.0f, e + 1.0f);
    return copysignf(r, xv);
}
__device__ __forceinline__ float comp2(float2 v, int c) { return c ? v.y : v.x; }

// stage x chunk starting at time ts into dst (transposed, duplicated pairs)
__device__ __forceinline__ void stage_x(ull (*dst)[CHUNK][32],
                                        const float* __restrict__ x,
                                        int b0, int st, int ts) {
    const int s = st / IN_D;
    const int i = st % IN_D;
    const float* gp = x + ((size_t)(b0 + s) * IN_D + i) * T_LEN + ts;
    const int rem = T_LEN - ts;
    if (rem >= CHUNK) {
        const float4* gp4 = (const float4*)gp;     // aligned: ts%16==0, row=4000B
        #pragma unroll
        for (int j4 = 0; j4 < CHUNK / 4; j4++) {
            float4 v = gp4[j4];
            dst[s][j4 * 4 + 0][i] = pk2(v.x, v.x);
            dst[s][j4 * 4 + 1][i] = pk2(v.y, v.y);
            dst[s][j4 * 4 + 2][i] = pk2(v.z, v.z);
            dst[s][j4 * 4 + 3][i] = pk2(v.w, v.w);
        }
    } else {
        for (int j = 0; j < rem; j++) dst[s][j][i] = pk2(gp[j], gp[j]);
    }
}

__global__ __launch_bounds__(NTHR, 1)
void lstm_fused(const float* __restrict__ x,
                const float* __restrict__ w_ih1, const float* __restrict__ w_hh1,
                const float* __restrict__ b_ih1, const float* __restrict__ b_hh1,
                const float* __restrict__ w_ih2, const float* __restrict__ w_hh2,
                const float* __restrict__ b_ih2, const float* __restrict__ b_hh2,
                const float* __restrict__ w_fc1, const float* __restrict__ b_fc1,
                const float* __restrict__ w_fc2, const float* __restrict__ b_fc2,
                float* __restrict__ out)
{
    // duplicated-pair activations
    __shared__ __align__(16) ull h1d[S_PER][H1_D];           // h1(t-1)
    __shared__ __align__(16) ull h2d[S_PER][H2_D];           // h2(t-2)
    __shared__ __align__(16) ull xsd[2][S_PER][CHUNK][32];   // x, double-buffered, padded
    // gate partials: [split][sample][row-pair] = {row 2p, row 2p+1}
    __shared__ __align__(16) ull g1p[3][S_PER][128];
    __shared__ __align__(16) ull g2p[3][S_PER][64];
    __shared__ __align__(16) float fcb[S_PER][F1_D];

    const int tid = threadIdx.x;
    const int b0  = blockIdx.x * S_PER;

    for (int i = tid; i < S_PER * H1_D; i += NTHR)           (&h1d[0][0])[i] = 0ULL;
    for (int i = tid; i < S_PER * H2_D; i += NTHR)           (&h2d[0][0])[i] = 0ULL;
    for (int i = tid; i < 2 * S_PER * CHUNK * 32; i += NTHR) (&xsd[0][0][0][0])[i] = 0ULL;

    // ---- per-thread weights: one row-pair x one 32-entry k-chunk (64 floats) ----
    // L1 (tid<384):   p = tid&127 (row-pair), split = tid>>7
    //   split0: k = x[0..32) (26 real)   split1: h1[0..32)   split2: h1[32..64)
    // L2 (tid>=384):  p = (tid-384)&63,  split = (tid-384)>>6
    //   split0: h1[0..32)   split1: h1[32..64)   split2: h2[0..32)
    ull w2[32];
    ull bias2 = 0ULL;
    float cst = 0.f;
    const bool isL1 = (tid < 384);
    int p, split;

    if (isL1) {
        p = tid & 127; split = tid >> 7;
        const int r0 = 2 * p, r1 = r0 + 1;
        if (split == 0) {
            #pragma unroll
            for (int k = 0; k < 32; k++)
                w2[k] = (k < 26) ? pk2(w_ih1[r0 * 26 + k], w_ih1[r1 * 26 + k]) : 0ULL;
            bias2 = pk2(b_ih1[r0] + b_hh1[r0], b_ih1[r1] + b_hh1[r1]);
        } else {
            const int off = (split - 1) * 32;
            #pragma unroll
            for (int k = 0; k < 32; k++)
                w2[k] = pk2(w_hh1[r0 * 64 + off + k], w_hh1[r1 * 64 + off + k]);
        }
    } else {
        const int q = tid - 384;
        p = q & 63; split = q >> 6;
        const int r0 = 2 * p, r1 = r0 + 1;
        if (split < 2) {
            const int off = split * 32;
            #pragma unroll
            for (int k = 0; k < 32; k++)
                w2[k] = pk2(w_ih2[r0 * 64 + off + k], w_ih2[r1 * 64 + off + k]);
            if (split == 0)
                bias2 = pk2(b_ih2[r0] + b_hh2[r0], b_ih2[r1] + b_hh2[r1]);
        } else {
            #pragma unroll
            for (int k = 0; k < 32; k++)
                w2[k] = pk2(w_hh2[r0 * 32 + k], w_hh2[r1 * 32 + k]);
        }
    }

    // stage chunk 0 into buffer 0
    if (tid < S_PER * IN_D) stage_x(xsd[0], x, b0, tid, 0);
    __syncthreads();

    // ---- time loop; L2 one step behind L1; t==T_LEN is the drain ----
    for (int t = 0; t <= T_LEN; t++) {
        const int tc  = t & (CHUNK - 1);
        const int buf = (t >> 4) & 1;

        // ---- PHASE A: packed partial gate dot-products (all 18 warps) ----
        if (isL1) {
            if (t < T_LEN) {
                #pragma unroll
                for (int s = 0; s < S_PER; s++) {
                    const ull* av = (split == 0) ? xsd[buf][s][tc]
                                                 : (h1d[s] + (split - 1) * 32);
                    const ulonglong2* av2 = (const ulonglong2*)av;
                    ull acc = bias2;
                    #pragma unroll
                    for (int k = 0; k < 16; k++) {
                        ulonglong2 v = av2[k];
                        acc = fma2(w2[2 * k],     v.x, acc);
                        acc = fma2(w2[2 * k + 1], v.y, acc);
                    }
                    g1p[split][s][p] = acc;
                }
            }
        } else {
            if (t >= 1) {
                #pragma unroll
                for (int s = 0; s < S_PER; s++) {
                    const ull* av = (split < 2) ? (h1d[s] + split * 32) : h2d[s];
                    const ulonglong2* av2 = (const ulonglong2*)av;
                    ull acc = bias2;
                    #pragma unroll
                    for (int k = 0; k < 16; k++) {
                        ulonglong2 v = av2[k];
                        acc = fma2(w2[2 * k],     v.x, acc);
                        acc = fma2(w2[2 * k + 1], v.y, acc);
                    }
                    g2p[split][s][p] = acc;
                }
            }
        }
        __syncthreads();

        // ---- PHASE B: cell updates + next-chunk staging on idle warps ----
        if (tid < 256) {
            if (t < T_LEN) {                       // layer-1 unit update -> h1(t)
                const int s = tid >> 6, u = tid & 63;
                const int pi = u >> 1, c = u & 1;
                float gi = comp2(unpk(g1p[0][s][pi]),      c) + comp2(unpk(g1p[1][s][pi]),      c) + comp2(unpk(g1p[2][s][pi]),      c);
                float gf = comp2(unpk(g1p[0][s][32 + pi]), c) + comp2(unpk(g1p[1][s][32 + pi]), c) + comp2(unpk(g1p[2][s][32 + pi]), c);
                float gg = comp2(unpk(g1p[0][s][64 + pi]), c) + comp2(unpk(g1p[1][s][64 + pi]), c) + comp2(unpk(g1p[2][s][64 + pi]), c);
                float go = comp2(unpk(g1p[0][s][96 + pi]), c) + comp2(unpk(g1p[1][s][96 + pi]), c) + comp2(unpk(g1p[2][s][96 + pi]), c);
                float ig = sigm(gi), fg = sigm(gf), g = tanh_(gg), og = sigm(go);
                cst = fg * cst + ig * g;
                float h = og * tanh_(cst);
                h1d[s][u] = pk2(h, h);
            }
        } else if (tid < 384) {
            // stage next chunk into the other buffer (warps 8-11 idle in B)
            if (tc == 0) {
                const int st = tid - 256;
                const int ts = t + CHUNK;
                if (st < S_PER * IN_D && ts < T_LEN)
                    stage_x(xsd[buf ^ 1], x, b0, st, ts);
            }
        } else if (tid < 512) {
            if (t >= 1) {                          // layer-2 unit update -> h2(t-1)
                const int q = tid - 384;
                const int s = q >> 5, u = q & 31;
                const int pi = u >> 1, c = u & 1;
                float gi = comp2(unpk(g2p[0][s][pi]),      c) + comp2(unpk(g2p[1][s][pi]),      c) + comp2(unpk(g2p[2][s][pi]),      c);
                float gf = comp2(unpk(g2p[0][s][16 + pi]), c) + comp2(unpk(g2p[1][s][16 + pi]), c) + comp2(unpk(g2p[2][s][16 + pi]), c);
                float gg = comp2(unpk(g2p[0][s][32 + pi]), c) + comp2(unpk(g2p[1][s][32 + pi]), c) + comp2(unpk(g2p[2][s][32 + pi]), c);
                float go = comp2(unpk(g2p[0][s][48 + pi]), c) + comp2(unpk(g2p[1][s][48 + pi]), c) + comp2(unpk(g2p[2][s][48 + pi]), c);
                float ig = sigm(gi), fg = sigm(gf), g = tanh_(gg), og = sigm(go);
                cst = fg * cst + ig * g;
                float h = og * tanh_(cst);
                h2d[s][u] = pk2(h, h);
            }
        }
        __syncthreads();
    }

    // ---- FC head ----
    if (tid < S_PER * F1_D) {
        const int s = tid / F1_D, j = tid % F1_D;
        float acc = b_fc1[j];
        #pragma unroll
        for (int k = 0; k < H2_D; k++) acc += w_fc1[j * H2_D + k] * unpk(h2d[s][k]).x;
        fcb[s][j] = fmaxf(acc, 0.f);
    }
    __syncthreads();
    if (tid < S_PER * OUT_D) {
        const int s = tid / OUT_D, j = tid % OUT_D;
        float acc = b_fc2[j];
        #pragma unroll
        for (int k = 0; k < F1_D; k++) acc += w_fc2[j * F1_D + k] * fcb[s][k];
        out[(b0 + s) * OUT_D + j] = acc;
    }
}

extern "C" void kernel_launch(void* const* d_in, const int* in_sizes, int n_in,
                              void* d_out, int out_size)
{
    lstm_fused<<<NBLK, NTHR>>>(
        (const float*)d_in[0],
        (const float*)d_in[1],  (const float*)d_in[2],
        (const float*)d_in[3],  (const float*)d_in[4],
        (const float*)d_in[5],  (const float*)d_in[6],
        (const float*)d_in[7],  (const float*)d_in[8],
        (const float*)d_in[9],  (const float*)d_in[10],
        (const float*)d_in[11], (const float*)d_in[12],
        (float*)d_out);
}